// round 14
// baseline (speedup 1.0000x reference)
#include <cuda_runtime.h>
#include <cuda_fp16.h>
#include <cuda_bf16.h>
#include <mma.h>
#include <cstdint>

using namespace nvcuda;

#define H   128
#define XD  64
#define ED  16
#define NMAX 50000
#define EMAX 640000
#define GPMAX 512
#define BN_EPS 1e-5f

// ---------------- scratch (static device globals; no allocation) ----------------
__device__ __align__(16) float g_h  [(size_t)NMAX * H];
__device__ __align__(16) float g_t  [(size_t)NMAX * H];
__device__ __align__(16) float g_h1 [(size_t)NMAX * H];
__device__ __align__(16) float g_pooled[GPMAX * H];
__device__ __align__(16) float g_colsum[H];
__device__ __align__(16) float g_colsumsq[H];
__device__ __align__(16) float g_scale[H];
__device__ __align__(16) float g_shift[H];
__device__ __align__(16) __half g_esort[(size_t)EMAX * H];   // 164 MB
__device__ int   g_ssrc [EMAX];
__device__ int   g_eperm[EMAX];
__device__ int   g_cnt  [NMAX];
__device__ int   g_row  [NMAX + 1];
__device__ int   g_ofs  [NMAX];

// ---------------- helpers ----------------
__device__ __forceinline__ void red_add_v4(float* addr, float4 v) {
    asm volatile("red.global.add.v4.f32 [%0], {%1,%2,%3,%4};"
                 :: "l"(addr), "f"(v.x), "f"(v.y), "f"(v.z), "f"(v.w)
                 : "memory");
}

#define FMA2(acc_, a_, b_) \
    asm("fma.rn.f32x2 %0, %1, %2, %0;" : "+l"(acc_) : "l"(a_), "l"(b_))

// ---------------- CSR build: histogram -> scan -> scatter ----------------
__global__ void hist_kernel(const int* __restrict__ ei, int* __restrict__ cnt, int E)
{
    int e = blockIdx.x * blockDim.x + threadIdx.x;
    if (e < E) atomicAdd(&cnt[__ldg(ei + E + e)], 1);
}

__global__ void prefix_kernel(const int* __restrict__ cnt, int* __restrict__ row_ptr,
                              int* __restrict__ ofs, int N, int E)
{
    __shared__ int ssum[1024];
    int tid = threadIdx.x;
    int per = (N + 1023) >> 10;
    int start = tid * per;
    int end = min(start + per, N);
    int s = 0;
    for (int i = start; i < end; i++) s += cnt[i];
    ssum[tid] = s;
    __syncthreads();
    #pragma unroll
    for (int off = 1; off < 1024; off <<= 1) {
        int v = (tid >= off) ? ssum[tid - off] : 0;
        __syncthreads();
        ssum[tid] += v;
        __syncthreads();
    }
    int run = (tid > 0) ? ssum[tid - 1] : 0;
    for (int i = start; i < end; i++) {
        row_ptr[i] = run;
        ofs[i] = run;
        run += cnt[i];
    }
    if (tid == 0) row_ptr[N] = E;
}

__global__ void scatter_kernel(const int* __restrict__ ei,
                               int* __restrict__ ofs, int* __restrict__ ssrc,
                               int* __restrict__ eperm, int E)
{
    int e = blockIdx.x * blockDim.x + threadIdx.x;
    if (e >= E) return;
    int dst = __ldg(ei + E + e);
    int pos = atomicAdd(&ofs[dst], 1);
    ssrc[pos] = __ldg(ei + e);
    eperm[pos] = e;
}

// ---------------- edge MLP precompute as tiled GEMM (ONCE), fp16 output ----------------
__global__ void __launch_bounds__(256, 2) ecomp_kernel(
    const float* __restrict__ ea, const int* __restrict__ eperm,
    const float* __restrict__ eW, const float* __restrict__ eb,
    __half* __restrict__ esort, int E)
{
    __shared__ __align__(16) float As[ED][132];
    __shared__ __align__(16) float Bs[ED][128];
    const int tid = threadIdx.x;
    const int tx  = tid & 15;
    const int ty  = tid >> 4;
    const int rowBlk = blockIdx.x * 128;

    {
        int idx = tid * 4;
        *(float4*)&Bs[idx >> 7][idx & 127] = *(const float4*)(eW + idx);
        idx += 1024;
        *(float4*)&Bs[idx >> 7][idx & 127] = *(const float4*)(eW + idx);
    }
    {
        int r = tid >> 1;
        int c0 = (tid & 1) * 8;
        int pos = rowBlk + r;
        float4 v0, v1;
        if (pos < E) {
            int e = __ldg(eperm + pos);
            const float4* ap = (const float4*)(ea + (size_t)e * ED + c0);
            v0 = __ldg(ap + 0);
            v1 = __ldg(ap + 1);
        } else {
            v0 = make_float4(0.f, 0.f, 0.f, 0.f);
            v1 = v0;
        }
        As[c0 + 0][r] = v0.x; As[c0 + 1][r] = v0.y;
        As[c0 + 2][r] = v0.z; As[c0 + 3][r] = v0.w;
        As[c0 + 4][r] = v1.x; As[c0 + 5][r] = v1.y;
        As[c0 + 6][r] = v1.z; As[c0 + 7][r] = v1.w;
    }
    __syncthreads();

    unsigned long long accP[8][4];
    #pragma unroll
    for (int r = 0; r < 8; r++)
        #pragma unroll
        for (int c = 0; c < 4; c++) accP[r][c] = 0ull;

    #pragma unroll
    for (int kk = 0; kk < ED; kk++) {
        float4 a0 = *(const float4*)&As[kk][ty * 8];
        float4 a1 = *(const float4*)&As[kk][ty * 8 + 4];
        ulonglong2 bq0 = *(const ulonglong2*)&Bs[kk][tx * 8];
        ulonglong2 bq1 = *(const ulonglong2*)&Bs[kk][tx * 8 + 4];
        unsigned long long bP0 = bq0.x, bP1 = bq0.y, bP2 = bq1.x, bP3 = bq1.y;
        float a[8] = {a0.x, a0.y, a0.z, a0.w, a1.x, a1.y, a1.z, a1.w};
        #pragma unroll
        for (int r = 0; r < 8; r++) {
            unsigned long long aP;
            asm("mov.b64 %0, {%1, %1};" : "=l"(aP) : "f"(a[r]));
            FMA2(accP[r][0], aP, bP0);
            FMA2(accP[r][1], aP, bP1);
            FMA2(accP[r][2], aP, bP2);
            FMA2(accP[r][3], aP, bP3);
        }
    }

    float bias_c[8];
    #pragma unroll
    for (int j = 0; j < 8; j++) bias_c[j] = __ldg(eb + tx * 8 + j);

    #pragma unroll
    for (int r = 0; r < 8; r++) {
        int pos = rowBlk + ty * 8 + r;
        if (pos < E) {
            float o[8];
            #pragma unroll
            for (int c = 0; c < 4; c++) {
                float lo, hi;
                asm("mov.b64 {%0, %1}, %2;" : "=f"(lo), "=f"(hi) : "l"(accP[r][c]));
                o[2 * c]     = lo + bias_c[2 * c];
                o[2 * c + 1] = hi + bias_c[2 * c + 1];
            }
            __half2 p0 = __floats2half2_rn(o[0], o[1]);
            __half2 p1 = __floats2half2_rn(o[2], o[3]);
            __half2 p2 = __floats2half2_rn(o[4], o[5]);
            __half2 p3 = __floats2half2_rn(o[6], o[7]);
            uint4 pk;
            pk.x = *(unsigned*)&p0; pk.y = *(unsigned*)&p1;
            pk.z = *(unsigned*)&p2; pk.w = *(unsigned*)&p3;
            *(uint4*)(esort + (size_t)pos * H + tx * 8) = pk;
        }
    }
}

// ------- aggregation (per layer) -------
__global__ void __launch_bounds__(256) aggr_kernel(
    const float* __restrict__ h, float* __restrict__ t,
    const __half* __restrict__ esort, const int* __restrict__ ssrc,
    const int* __restrict__ row_ptr, int N,
    float* __restrict__ cs, float* __restrict__ cq)
{
    if (blockIdx.x == 0 && threadIdx.x < H) { cs[threadIdx.x] = 0.f; cq[threadIdx.x] = 0.f; }

    const int lane = threadIdx.x & 31;
    const int f = lane * 4;
    int n = (blockIdx.x * blockDim.x + threadIdx.x) >> 5;
    if (n >= N) return;

    int beg = __ldg(row_ptr + n);
    int end = __ldg(row_ptr + n + 1);
    float4 acc = *(const float4*)(h + (size_t)n * H + f);

    int pos = beg;
    for (; pos + 2 <= end; pos += 2) {
        int s0 = __ldg(ssrc + pos);
        int s1 = __ldg(ssrc + pos + 1);
        uint2 er0 = __ldg((const uint2*)(esort + (size_t)pos * H + f));
        uint2 er1 = __ldg((const uint2*)(esort + (size_t)(pos + 1) * H + f));
        float4 h0 = *(const float4*)(h + (size_t)s0 * H + f);
        float4 h1 = *(const float4*)(h + (size_t)s1 * H + f);
        float2 e0a = __half22float2(*(const __half2*)&er0.x);
        float2 e0b = __half22float2(*(const __half2*)&er0.y);
        float2 e1a = __half22float2(*(const __half2*)&er1.x);
        float2 e1b = __half22float2(*(const __half2*)&er1.y);
        acc.x += fmaxf(h0.x + e0a.x, 0.f) + fmaxf(h1.x + e1a.x, 0.f);
        acc.y += fmaxf(h0.y + e0a.y, 0.f) + fmaxf(h1.y + e1a.y, 0.f);
        acc.z += fmaxf(h0.z + e0b.x, 0.f) + fmaxf(h1.z + e1b.x, 0.f);
        acc.w += fmaxf(h0.w + e0b.y, 0.f) + fmaxf(h1.w + e1b.y, 0.f);
    }
    if (pos < end) {
        int s0 = __ldg(ssrc + pos);
        uint2 er0 = __ldg((const uint2*)(esort + (size_t)pos * H + f));
        float4 h0 = *(const float4*)(h + (size_t)s0 * H + f);
        float2 e0a = __half22float2(*(const __half2*)&er0.x);
        float2 e0b = __half22float2(*(const __half2*)&er0.y);
        acc.x += fmaxf(h0.x + e0a.x, 0.f);
        acc.y += fmaxf(h0.y + e0a.y, 0.f);
        acc.z += fmaxf(h0.z + e0b.x, 0.f);
        acc.w += fmaxf(h0.w + e0b.y, 0.f);
    }
    *(float4*)(t + (size_t)n * H + f) = acc;
}

// ---------------- wmma bf16 split GEMM: C[M,128] = op(A[M,128]) @ W[128,128] + bias ----
// 3-product split (AhiBhi + AhiBlo + AloBhi) ~ fp32-quality. Tensor cores via HMMA.
// smem: Ahi/Alo/Bhi/Blo [128][128] bf16 + biasRows [16][128] f32 = 136 KB dynamic.
#define WM_SMEM (4 * 128 * 128 * 2 + 16 * 128 * 4)

template<bool BN_IN, bool RELU_OUT>
__global__ void __launch_bounds__(256) gemm_wmma(
    const float* __restrict__ A, const float* __restrict__ W,
    const float* __restrict__ bias, float* __restrict__ C, int M,
    const float* __restrict__ bscale, const float* __restrict__ bshift)
{
    extern __shared__ char smem[];
    __nv_bfloat16* Ahi = (__nv_bfloat16*)smem;
    __nv_bfloat16* Alo = Ahi + 128 * 128;
    __nv_bfloat16* Bhi = Alo + 128 * 128;
    __nv_bfloat16* Blo = Bhi + 128 * 128;
    float* biasRows = (float*)(Blo + 128 * 128);   // [16][128]

    const int tid = threadIdx.x;
    const int w = tid >> 5;              // warp -> output tile column (0..7)
    const int rowBlk = blockIdx.x * 128;

    // bias broadcast tile (16 identical rows)
    for (int i = tid; i < 16 * 128; i += 256)
        biasRows[i] = __ldg(bias + (i & 127));

    // ---- load + split A tile (optionally BN+relu) ----
    for (int idx = tid * 4; idx < 128 * 128; idx += 256 * 4) {
        int r = idx >> 7, c = idx & 127;
        int grow = rowBlk + r;
        float4 v = make_float4(0.f, 0.f, 0.f, 0.f);
        if (grow < M) {
            v = *(const float4*)(A + (size_t)grow * 128 + c);
            if (BN_IN) {
                v.x = fmaxf(v.x * __ldg(bscale + c + 0) + __ldg(bshift + c + 0), 0.f);
                v.y = fmaxf(v.y * __ldg(bscale + c + 1) + __ldg(bshift + c + 1), 0.f);
                v.z = fmaxf(v.z * __ldg(bscale + c + 2) + __ldg(bshift + c + 2), 0.f);
                v.w = fmaxf(v.w * __ldg(bscale + c + 3) + __ldg(bshift + c + 3), 0.f);
            }
        }
        float f[4] = {v.x, v.y, v.z, v.w};
        __nv_bfloat16 hi[4], lo[4];
        #pragma unroll
        for (int j = 0; j < 4; j++) {
            hi[j] = __float2bfloat16(f[j]);
            lo[j] = __float2bfloat16(f[j] - __bfloat162float(hi[j]));
        }
        *(__nv_bfloat162*)(Ahi + idx)     = __nv_bfloat162(hi[0], hi[1]);
        *(__nv_bfloat162*)(Ahi + idx + 2) = __nv_bfloat162(hi[2], hi[3]);
        *(__nv_bfloat162*)(Alo + idx)     = __nv_bfloat162(lo[0], lo[1]);
        *(__nv_bfloat162*)(Alo + idx + 2) = __nv_bfloat162(lo[2], lo[3]);
    }
    // ---- load + split W (row-major [K][N] = wmma matrix_b row_major directly) ----
    for (int idx = tid * 4; idx < 128 * 128; idx += 256 * 4) {
        float4 v = __ldg((const float4*)(W + idx));
        float f[4] = {v.x, v.y, v.z, v.w};
        __nv_bfloat16 hi[4], lo[4];
        #pragma unroll
        for (int j = 0; j < 4; j++) {
            hi[j] = __float2bfloat16(f[j]);
            lo[j] = __float2bfloat16(f[j] - __bfloat162float(hi[j]));
        }
        *(__nv_bfloat162*)(Bhi + idx)     = __nv_bfloat162(hi[0], hi[1]);
        *(__nv_bfloat162*)(Bhi + idx + 2) = __nv_bfloat162(hi[2], hi[3]);
        *(__nv_bfloat162*)(Blo + idx)     = __nv_bfloat162(lo[0], lo[1]);
        *(__nv_bfloat162*)(Blo + idx + 2) = __nv_bfloat162(lo[2], lo[3]);
    }
    __syncthreads();

    // ---- accumulate: 8 row-tiles per warp, fixed column tile w ----
    wmma::fragment<wmma::accumulator, 16, 16, 16, float> cf[8];
    #pragma unroll
    for (int tr = 0; tr < 8; tr++)
        wmma::load_matrix_sync(cf[tr], biasRows + w * 16, 128, wmma::mem_row_major);
    __syncthreads();   // biasRows may be reused as epilogue scratch

    for (int k = 0; k < 8; k++) {
        wmma::fragment<wmma::matrix_b, 16, 16, 16, __nv_bfloat16, wmma::row_major> bh, bl;
        wmma::load_matrix_sync(bh, Bhi + (k * 16) * 128 + w * 16, 128);
        wmma::load_matrix_sync(bl, Blo + (k * 16) * 128 + w * 16, 128);
        #pragma unroll
        for (int tr = 0; tr < 8; tr++) {
            wmma::fragment<wmma::matrix_a, 16, 16, 16, __nv_bfloat16, wmma::row_major> ah, al;
            wmma::load_matrix_sync(ah, Ahi + (tr * 16) * 128 + k * 16, 128);
            wmma::load_matrix_sync(al, Alo + (tr * 16) * 128 + k * 16, 128);
            wmma::mma_sync(cf[tr], ah, bh, cf[tr]);
            wmma::mma_sync(cf[tr], ah, bl, cf[tr]);
            wmma::mma_sync(cf[tr], al, bh, cf[tr]);
        }
    }

    // ---- epilogue ----
    #pragma unroll
    for (int tr = 0; tr < 8; tr++) {
        int grow = rowBlk + tr * 16;
        if (grow >= M) break;
        if (RELU_OUT) {
            #pragma unroll
            for (int i = 0; i < cf[tr].num_elements; i++)
                cf[tr].x[i] = fmaxf(cf[tr].x[i], 0.f);
        }
        if (grow + 16 <= M) {
            wmma::store_matrix_sync(C + (size_t)grow * 128 + w * 16, cf[tr], 128,
                                    wmma::mem_row_major);
        } else {
            // partial tile: stage via scratch (per-warp region of biasRows)
            float* scr = biasRows + w * 256;
            wmma::store_matrix_sync(scr, cf[tr], 16, wmma::mem_row_major);
            int lane = tid & 31;
            for (int i = lane; i < 16 * 16; i += 32) {
                int rr = i >> 4;
                if (grow + rr < M) C[(size_t)(grow + rr) * 128 + w * 16 + (i & 15)] = scr[i];
            }
        }
    }
}

// ---------------- column stats over C[M,128] (for BN) ----------------
__global__ void __launch_bounds__(128) stats_kernel(
    const float* __restrict__ C, int M,
    float* __restrict__ gsum, float* __restrict__ gsq)
{
    int col = threadIdx.x;
    int r0 = blockIdx.x * 128;
    int r1 = min(r0 + 128, M);
    float s = 0.f, q = 0.f;
    for (int r = r0; r < r1; r++) {
        float v = C[(size_t)r * 128 + col];
        s += v; q += v * v;
    }
    atomicAdd(gsum + col, s);
    atomicAdd(gsq + col, q);
}

// ---------------- FMA2 SGEMM (encoder only, K=64) ----------------
template<int K>
__global__ void __launch_bounds__(256, 2) gemm_k(
    const float* __restrict__ A, const float* __restrict__ W,
    const float* __restrict__ bias, float* __restrict__ C, int M)
{
    constexpr int NT = K / 8;
    __shared__ __align__(16) float As[2][8][132];
    __shared__ __align__(16) float Bs[2][8][128];

    const int tid = threadIdx.x;
    const int tx  = tid & 15;
    const int ty  = tid >> 4;
    const int rowBlk = blockIdx.x * 128;

    const int aRow = tid >> 1;
    const int aK   = (tid & 1) << 2;
    const int wK   = tid >> 5;
    const int wN   = (tid & 31) << 2;

    unsigned long long accP[8][4];
    #pragma unroll
    for (int r = 0; r < 8; r++)
        #pragma unroll
        for (int c = 0; c < 4; c++) accP[r][c] = 0ull;

    float4 va, vb;
    {
        int grow = rowBlk + aRow;
        if (grow < M) va = *(const float4*)(A + (size_t)grow * K + aK);
        else va = make_float4(0.f, 0.f, 0.f, 0.f);
        vb = *(const float4*)(W + (size_t)wK * 128 + wN);
    }
    As[0][aK + 0][aRow] = va.x;
    As[0][aK + 1][aRow] = va.y;
    As[0][aK + 2][aRow] = va.z;
    As[0][aK + 3][aRow] = va.w;
    *(float4*)&Bs[0][wK][wN] = vb;
    __syncthreads();

    for (int kt = 0; kt < NT; kt++) {
        const int cur = kt & 1;
        if (kt + 1 < NT) {
            int gk = (kt + 1) * 8;
            int grow = rowBlk + aRow;
            if (grow < M) va = *(const float4*)(A + (size_t)grow * K + gk + aK);
            else va = make_float4(0.f, 0.f, 0.f, 0.f);
            vb = *(const float4*)(W + (size_t)(gk + wK) * 128 + wN);
        }
        #pragma unroll
        for (int kk = 0; kk < 8; kk++) {
            float4 a0 = *(const float4*)&As[cur][kk][ty * 8];
            float4 a1 = *(const float4*)&As[cur][kk][ty * 8 + 4];
            ulonglong2 bq0 = *(const ulonglong2*)&Bs[cur][kk][tx * 8];
            ulonglong2 bq1 = *(const ulonglong2*)&Bs[cur][kk][tx * 8 + 4];
            unsigned long long bP0 = bq0.x, bP1 = bq0.y, bP2 = bq1.x, bP3 = bq1.y;
            float a[8] = {a0.x, a0.y, a0.z, a0.w, a1.x, a1.y, a1.z, a1.w};
            #pragma unroll
            for (int r = 0; r < 8; r++) {
                unsigned long long aP;
                asm("mov.b64 %0, {%1, %1};" : "=l"(aP) : "f"(a[r]));
                FMA2(accP[r][0], aP, bP0);
                FMA2(accP[r][1], aP, bP1);
                FMA2(accP[r][2], aP, bP2);
                FMA2(accP[r][3], aP, bP3);
            }
        }
        if (kt + 1 < NT) {
            const int nxt = cur ^ 1;
            As[nxt][aK + 0][aRow] = va.x;
            As[nxt][aK + 1][aRow] = va.y;
            As[nxt][aK + 2][aRow] = va.z;
            As[nxt][aK + 3][aRow] = va.w;
            *(float4*)&Bs[nxt][wK][wN] = vb;
        }
        __syncthreads();
    }

    float bias_c[8];
    #pragma unroll
    for (int j = 0; j < 8; j++) bias_c[j] = __ldg(bias + tx * 8 + j);

    #pragma unroll
    for (int r = 0; r < 8; r++) {
        int grow = rowBlk + ty * 8 + r;
        if (grow < M) {
            float o[8];
            #pragma unroll
            for (int c = 0; c < 4; c++) {
                float lo, hi;
                asm("mov.b64 {%0, %1}, %2;" : "=f"(lo), "=f"(hi) : "l"(accP[r][c]));
                o[2 * c]     = lo + bias_c[2 * c];
                o[2 * c + 1] = hi + bias_c[2 * c + 1];
            }
            *(float4*)(C + (size_t)grow * 128 + tx * 8)     = make_float4(o[0], o[1], o[2], o[3]);
            *(float4*)(C + (size_t)grow * 128 + tx * 8 + 4) = make_float4(o[4], o[5], o[6], o[7]);
        }
    }
}

// ---------------- BN finalize ----------------
__global__ void bn_finalize_kernel(const float* __restrict__ cs, const float* __restrict__ cq,
                                   const float* __restrict__ g, const float* __restrict__ b,
                                   int N, float* __restrict__ scale, float* __restrict__ shift)
{
    int j = threadIdx.x;
    float invN = 1.f / (float)N;
    float mean = cs[j] * invN;
    float var  = cq[j] * invN - mean * mean;
    float inv  = rsqrtf(var + BN_EPS);
    float sc   = g[j] * inv;
    scale[j] = sc;
    shift[j] = b[j] - mean * sc;
}

// ---------------- global add pool ----------------
__global__ void __launch_bounds__(256) pool_kernel(
    const float* __restrict__ h, const int* __restrict__ batch,
    float* __restrict__ pooled, int N)
{
    const int lane = threadIdx.x & 31;
    const int warp = (blockIdx.x * blockDim.x + threadIdx.x) >> 5;
    const int CHUNK = 64;
    int n0 = warp * CHUNK;
    if (n0 >= N) return;
    int n1 = n0 + CHUNK; if (n1 > N) n1 = N;
    const int f = lane * 4;

    int cur = __ldg(batch + n0);
    float4 acc = make_float4(0.f, 0.f, 0.f, 0.f);
    for (int n = n0; n < n1; n++) {
        int b = __ldg(batch + n);
        if (b != cur) {
            red_add_v4(pooled + (size_t)cur * H + f, acc);
            acc = make_float4(0.f, 0.f, 0.f, 0.f);
            cur = b;
        }
        float4 v = *(const float4*)(h + (size_t)n * H + f);
        acc.x += v.x; acc.y += v.y; acc.z += v.z; acc.w += v.w;
    }
    red_add_v4(pooled + (size_t)cur * H + f, acc);
}

// ---------------- final FC ----------------
__global__ void final_gemm_kernel(const float* __restrict__ pooled,
                                  const float* __restrict__ fcw, const float* __restrict__ fcb,
                                  float* __restrict__ out, int G)
{
    __shared__ float row[H];
    int g = blockIdx.x;
    row[threadIdx.x] = pooled[(size_t)g * H + threadIdx.x];
    __syncthreads();
    if (threadIdx.x < 10) {
        float acc = fcb[threadIdx.x];
        #pragma unroll 8
        for (int k = 0; k < H; k++)
            acc += row[k] * fcw[k * 10 + threadIdx.x];
        out[g * 10 + threadIdx.x] = acc;
    }
}

// ---------------- launch ----------------
extern "C" void kernel_launch(void* const* d_in, const int* in_sizes, int n_in,
                              void* d_out, int out_size)
{
    const float* x      = (const float*)d_in[0];
    const float* ea     = (const float*)d_in[1];
    const float* node_w = (const float*)d_in[2];
    const float* node_b = (const float*)d_in[3];
    const float* edge_w = (const float*)d_in[4];
    const float* edge_b = (const float*)d_in[5];
    const float* lin1_w = (const float*)d_in[6];
    const float* lin1_b = (const float*)d_in[7];
    const float* bn_g   = (const float*)d_in[8];
    const float* bn_b   = (const float*)d_in[9];
    const float* lin2_w = (const float*)d_in[10];
    const float* lin2_b = (const float*)d_in[11];
    const float* fc_w   = (const float*)d_in[12];
    const float* fc_b   = (const float*)d_in[13];
    const int* ei       = (const int*)d_in[14];
    const int* batch    = (const int*)d_in[15];

    const int N = in_sizes[0] / XD;
    const int E = in_sizes[1] / ED;
    const int G = out_size / 10;

    float *hP, *tP, *h1P, *plP, *csP, *cqP, *scP, *shP;
    __half* esP;
    int *ssrcP, *epermP, *cntP, *rowP, *ofsP;
    cudaGetSymbolAddress((void**)&hP,    g_h);
    cudaGetSymbolAddress((void**)&tP,    g_t);
    cudaGetSymbolAddress((void**)&h1P,   g_h1);
    cudaGetSymbolAddress((void**)&plP,   g_pooled);
    cudaGetSymbolAddress((void**)&csP,   g_colsum);
    cudaGetSymbolAddress((void**)&cqP,   g_colsumsq);
    cudaGetSymbolAddress((void**)&scP,   g_scale);
    cudaGetSymbolAddress((void**)&shP,   g_shift);
    cudaGetSymbolAddress((void**)&esP,   g_esort);
    cudaGetSymbolAddress((void**)&ssrcP, g_ssrc);
    cudaGetSymbolAddress((void**)&epermP,g_eperm);
    cudaGetSymbolAddress((void**)&cntP,  g_cnt);
    cudaGetSymbolAddress((void**)&rowP,  g_row);
    cudaGetSymbolAddress((void**)&ofsP,  g_ofs);

    // opt-in to 136KB dynamic smem for wmma GEMM (host-side attr, capture-safe)
    cudaFuncSetAttribute(gemm_wmma<false, false>, cudaFuncAttributeMaxDynamicSharedMemorySize, WM_SMEM);
    cudaFuncSetAttribute(gemm_wmma<true, true>,   cudaFuncAttributeMaxDynamicSharedMemorySize, WM_SMEM);

    const int gemmGrid = (N + 127) / 128;

    // ---- CSR build + edge-MLP precompute (ONCE) ----
    cudaMemsetAsync(cntP, 0, N * sizeof(int));
    hist_kernel<<<(E + 255) / 256, 256>>>(ei, cntP, E);
    prefix_kernel<<<1, 1024>>>(cntP, rowP, ofsP, N, E);
    scatter_kernel<<<(E + 255) / 256, 256>>>(ei, ofsP, ssrcP, epermP, E);
    ecomp_kernel<<<(E + 127) / 128, 256>>>(ea, epermP, edge_w, edge_b, esP, E);

    // node encoder: h = x @ node_w + node_b  (FMA2 path, K=64)
    gemm_k<XD><<<gemmGrid, 256>>>(x, node_w, node_b, hP, N);

    for (int l = 0; l < 3; l++) {
        // t = h + segment_sum(relu(h[src] + e)); zeroes BN stat accumulators
        aggr_kernel<<<(N * 32 + 255) / 256, 256>>>(
            hP, tP, esP, ssrcP, rowP, N, csP, cqP);
        // h1 = t @ W1 + b1   (wmma bf16-split tensor cores)
        gemm_wmma<false, false><<<gemmGrid, 256, WM_SMEM>>>(
            tP, lin1_w + (size_t)l * H * H, lin1_b + l * H, h1P, N, nullptr, nullptr);
        // column stats of h1
        stats_kernel<<<gemmGrid, 128>>>(h1P, N, csP, cqP);
        // BN scale/shift
        bn_finalize_kernel<<<1, H>>>(csP, cqP, bn_g + l * H, bn_b + l * H, N, scP, shP);
        // h = relu( relu(bn(h1)) @ W2 + b2 )   (wmma bf16-split tensor cores)
        gemm_wmma<true, true><<<gemmGrid, 256, WM_SMEM>>>(
            h1P, lin2_w + (size_t)l * H * H, lin2_b + l * H, hP, N, scP, shP);
    }

    // pooled = segment_sum(h, batch)
    cudaMemsetAsync(plP, 0, (size_t)G * H * sizeof(float));
    int poolWarps = (N + 63) / 64;
    pool_kernel<<<(poolWarps + 7) / 8, 256>>>(hP, batch, plP, N);

    // out = pooled @ fc_w + fc_b
    final_gemm_kernel<<<G, H>>>(plP, fc_w, fc_b, (float*)d_out, G);
}

// round 15
// speedup vs baseline: 1.2775x; 1.2775x over previous
#include <cuda_runtime.h>
#include <cuda_fp16.h>
#include <cstdint>

#define H   128
#define XD  64
#define ED  16
#define NMAX 50000
#define EMAX 640000
#define GPMAX 512
#define BN_EPS 1e-5f

// ---------------- scratch (static device globals; no allocation) ----------------
__device__ __align__(16) float g_h  [(size_t)NMAX * H];
__device__ __align__(16) float g_t  [(size_t)NMAX * H];
__device__ __align__(16) float g_h1 [(size_t)NMAX * H];
__device__ __align__(16) float g_pooled[GPMAX * H];
__device__ __align__(16) float g_colsum[H];
__device__ __align__(16) float g_colsumsq[H];
__device__ __align__(16) float g_scale[H];
__device__ __align__(16) float g_shift[H];
// edge features precomputed ONCE (layer-invariant), dst-sorted, fp16
__device__ __align__(16) __half g_esort[(size_t)EMAX * H];   // 164 MB
__device__ int   g_ssrc [EMAX];
__device__ int   g_eperm[EMAX];
__device__ int   g_cnt  [NMAX];
__device__ int   g_row  [NMAX + 1];
__device__ int   g_ofs  [NMAX];

// ---------------- helpers ----------------
__device__ __forceinline__ void red_add_v4(float* addr, float4 v) {
    asm volatile("red.global.add.v4.f32 [%0], {%1,%2,%3,%4};"
                 :: "l"(addr), "f"(v.x), "f"(v.y), "f"(v.z), "f"(v.w)
                 : "memory");
}

#define FMA2(acc_, a_, b_) \
    asm("fma.rn.f32x2 %0, %1, %2, %0;" : "+l"(acc_) : "l"(a_), "l"(b_))

// ---------------- CSR build: histogram -> scan -> scatter ----------------
__global__ void hist_kernel(const int* __restrict__ ei, int* __restrict__ cnt, int E)
{
    int e = blockIdx.x * blockDim.x + threadIdx.x;
    if (e < E) atomicAdd(&cnt[__ldg(ei + E + e)], 1);
}

__global__ void prefix_kernel(const int* __restrict__ cnt, int* __restrict__ row_ptr,
                              int* __restrict__ ofs, int N, int E)
{
    __shared__ int ssum[1024];
    int tid = threadIdx.x;
    int per = (N + 1023) >> 10;
    int start = tid * per;
    int end = min(start + per, N);
    int s = 0;
    for (int i = start; i < end; i++) s += cnt[i];
    ssum[tid] = s;
    __syncthreads();
    #pragma unroll
    for (int off = 1; off < 1024; off <<= 1) {
        int v = (tid >= off) ? ssum[tid - off] : 0;
        __syncthreads();
        ssum[tid] += v;
        __syncthreads();
    }
    int run = (tid > 0) ? ssum[tid - 1] : 0;
    for (int i = start; i < end; i++) {
        row_ptr[i] = run;
        ofs[i] = run;
        run += cnt[i];
    }
    if (tid == 0) row_ptr[N] = E;
}

__global__ void scatter_kernel(const int* __restrict__ ei,
                               int* __restrict__ ofs, int* __restrict__ ssrc,
                               int* __restrict__ eperm, int E)
{
    int e = blockIdx.x * blockDim.x + threadIdx.x;
    if (e >= E) return;
    int dst = __ldg(ei + E + e);
    int pos = atomicAdd(&ofs[dst], 1);
    ssrc[pos] = __ldg(ei + e);
    eperm[pos] = e;
}

// ---------------- edge MLP precompute as tiled GEMM (ONCE), fp16 output ----------------
__global__ void __launch_bounds__(256, 2) ecomp_kernel(
    const float* __restrict__ ea, const int* __restrict__ eperm,
    const float* __restrict__ eW, const float* __restrict__ eb,
    __half* __restrict__ esort, int E)
{
    __shared__ __align__(16) float As[ED][132];
    __shared__ __align__(16) float Bs[ED][128];
    const int tid = threadIdx.x;
    const int tx  = tid & 15;
    const int ty  = tid >> 4;
    const int rowBlk = blockIdx.x * 128;

    {
        int idx = tid * 4;
        *(float4*)&Bs[idx >> 7][idx & 127] = *(const float4*)(eW + idx);
        idx += 1024;
        *(float4*)&Bs[idx >> 7][idx & 127] = *(const float4*)(eW + idx);
    }
    {
        int r = tid >> 1;
        int c0 = (tid & 1) * 8;
        int pos = rowBlk + r;
        float4 v0, v1;
        if (pos < E) {
            int e = __ldg(eperm + pos);
            const float4* ap = (const float4*)(ea + (size_t)e * ED + c0);
            v0 = __ldg(ap + 0);
            v1 = __ldg(ap + 1);
        } else {
            v0 = make_float4(0.f, 0.f, 0.f, 0.f);
            v1 = v0;
        }
        As[c0 + 0][r] = v0.x; As[c0 + 1][r] = v0.y;
        As[c0 + 2][r] = v0.z; As[c0 + 3][r] = v0.w;
        As[c0 + 4][r] = v1.x; As[c0 + 5][r] = v1.y;
        As[c0 + 6][r] = v1.z; As[c0 + 7][r] = v1.w;
    }
    __syncthreads();

    unsigned long long accP[8][4];
    #pragma unroll
    for (int r = 0; r < 8; r++)
        #pragma unroll
        for (int c = 0; c < 4; c++) accP[r][c] = 0ull;

    #pragma unroll
    for (int kk = 0; kk < ED; kk++) {
        float4 a0 = *(const float4*)&As[kk][ty * 8];
        float4 a1 = *(const float4*)&As[kk][ty * 8 + 4];
        ulonglong2 bq0 = *(const ulonglong2*)&Bs[kk][tx * 8];
        ulonglong2 bq1 = *(const ulonglong2*)&Bs[kk][tx * 8 + 4];
        unsigned long long bP0 = bq0.x, bP1 = bq0.y, bP2 = bq1.x, bP3 = bq1.y;
        float a[8] = {a0.x, a0.y, a0.z, a0.w, a1.x, a1.y, a1.z, a1.w};
        #pragma unroll
        for (int r = 0; r < 8; r++) {
            unsigned long long aP;
            asm("mov.b64 %0, {%1, %1};" : "=l"(aP) : "f"(a[r]));
            FMA2(accP[r][0], aP, bP0);
            FMA2(accP[r][1], aP, bP1);
            FMA2(accP[r][2], aP, bP2);
            FMA2(accP[r][3], aP, bP3);
        }
    }

    float bias_c[8];
    #pragma unroll
    for (int j = 0; j < 8; j++) bias_c[j] = __ldg(eb + tx * 8 + j);

    #pragma unroll
    for (int r = 0; r < 8; r++) {
        int pos = rowBlk + ty * 8 + r;
        if (pos < E) {
            float o[8];
            #pragma unroll
            for (int c = 0; c < 4; c++) {
                float lo, hi;
                asm("mov.b64 {%0, %1}, %2;" : "=f"(lo), "=f"(hi) : "l"(accP[r][c]));
                o[2 * c]     = lo + bias_c[2 * c];
                o[2 * c + 1] = hi + bias_c[2 * c + 1];
            }
            __half2 p0 = __floats2half2_rn(o[0], o[1]);
            __half2 p1 = __floats2half2_rn(o[2], o[3]);
            __half2 p2 = __floats2half2_rn(o[4], o[5]);
            __half2 p3 = __floats2half2_rn(o[6], o[7]);
            uint4 pk;
            pk.x = *(unsigned*)&p0; pk.y = *(unsigned*)&p1;
            pk.z = *(unsigned*)&p2; pk.w = *(unsigned*)&p3;
            *(uint4*)(esort + (size_t)pos * H + tx * 8) = pk;
        }
    }
}

// ------- aggregation (per layer): t[n] = h[n] + sum_{pos in row n} relu(h[ssrc[pos]] + esort[pos]) ------
__global__ void __launch_bounds__(256) aggr_kernel(
    const float* __restrict__ h, float* __restrict__ t,
    const __half* __restrict__ esort, const int* __restrict__ ssrc,
    const int* __restrict__ row_ptr, int N,
    float* __restrict__ cs, float* __restrict__ cq)
{
    if (blockIdx.x == 0 && threadIdx.x < H) { cs[threadIdx.x] = 0.f; cq[threadIdx.x] = 0.f; }

    const int lane = threadIdx.x & 31;
    const int f = lane * 4;
    int n = (blockIdx.x * blockDim.x + threadIdx.x) >> 5;
    if (n >= N) return;

    int beg = __ldg(row_ptr + n);
    int end = __ldg(row_ptr + n + 1);
    float4 acc = *(const float4*)(h + (size_t)n * H + f);

    int pos = beg;
    for (; pos + 2 <= end; pos += 2) {
        int s0 = __ldg(ssrc + pos);
        int s1 = __ldg(ssrc + pos + 1);
        uint2 er0 = __ldg((const uint2*)(esort + (size_t)pos * H + f));
        uint2 er1 = __ldg((const uint2*)(esort + (size_t)(pos + 1) * H + f));
        float4 h0 = *(const float4*)(h + (size_t)s0 * H + f);
        float4 h1 = *(const float4*)(h + (size_t)s1 * H + f);
        float2 e0a = __half22float2(*(const __half2*)&er0.x);
        float2 e0b = __half22float2(*(const __half2*)&er0.y);
        float2 e1a = __half22float2(*(const __half2*)&er1.x);
        float2 e1b = __half22float2(*(const __half2*)&er1.y);
        acc.x += fmaxf(h0.x + e0a.x, 0.f) + fmaxf(h1.x + e1a.x, 0.f);
        acc.y += fmaxf(h0.y + e0a.y, 0.f) + fmaxf(h1.y + e1a.y, 0.f);
        acc.z += fmaxf(h0.z + e0b.x, 0.f) + fmaxf(h1.z + e1b.x, 0.f);
        acc.w += fmaxf(h0.w + e0b.y, 0.f) + fmaxf(h1.w + e1b.y, 0.f);
    }
    if (pos < end) {
        int s0 = __ldg(ssrc + pos);
        uint2 er0 = __ldg((const uint2*)(esort + (size_t)pos * H + f));
        float4 h0 = *(const float4*)(h + (size_t)s0 * H + f);
        float2 e0a = __half22float2(*(const __half2*)&er0.x);
        float2 e0b = __half22float2(*(const __half2*)&er0.y);
        acc.x += fmaxf(h0.x + e0a.x, 0.f);
        acc.y += fmaxf(h0.y + e0a.y, 0.f);
        acc.z += fmaxf(h0.z + e0b.x, 0.f);
        acc.w += fmaxf(h0.w + e0b.y, 0.f);
    }
    *(float4*)(t + (size_t)n * H + f) = acc;
}

// ---------------- tiled SGEMM with packed f32x2 FMA (pre-duplicated A in smem) ----------------
// C[M,128] = op(A[M,K]) @ W[K,128] + bias
// A tile stored as float2(v,v): packed FMA2 A-operand loaded directly, no mov.b64 packing.
template<int K, bool BN_IN, bool RELU_OUT, bool STATS>
__global__ void __launch_bounds__(256, 2) gemm_k(
    const float* __restrict__ A, const float* __restrict__ W,
    const float* __restrict__ bias, float* __restrict__ C, int M,
    const float* __restrict__ bscale, const float* __restrict__ bshift,
    float* __restrict__ gsum, float* __restrict__ gsq)
{
    constexpr int NT = K / 8;
    __shared__ __align__(16) float2 As2[2][8][130];   // duplicated pairs
    __shared__ __align__(16) float  Bs [2][8][128];
    __shared__ float s_sum[128];
    __shared__ float s_sq[128];

    const int tid = threadIdx.x;
    const int tx  = tid & 15;
    const int ty  = tid >> 4;
    const int rowBlk = blockIdx.x * 128;

    if (STATS && tid < 128) { s_sum[tid] = 0.f; s_sq[tid] = 0.f; }

    const int aRow = tid >> 1;
    const int aK   = (tid & 1) << 2;
    const int wK   = tid >> 5;
    const int wN   = (tid & 31) << 2;

    unsigned long long accP[8][4];
    #pragma unroll
    for (int r = 0; r < 8; r++)
        #pragma unroll
        for (int c = 0; c < 4; c++) accP[r][c] = 0ull;

    float4 va, vb;
    {
        int grow = rowBlk + aRow;
        if (grow < M) {
            va = *(const float4*)(A + (size_t)grow * K + aK);
            if (BN_IN) {
                int kb = aK;
                va.x = fmaxf(va.x * __ldg(bscale + kb + 0) + __ldg(bshift + kb + 0), 0.f);
                va.y = fmaxf(va.y * __ldg(bscale + kb + 1) + __ldg(bshift + kb + 1), 0.f);
                va.z = fmaxf(va.z * __ldg(bscale + kb + 2) + __ldg(bshift + kb + 2), 0.f);
                va.w = fmaxf(va.w * __ldg(bscale + kb + 3) + __ldg(bshift + kb + 3), 0.f);
            }
        } else va = make_float4(0.f, 0.f, 0.f, 0.f);
        vb = *(const float4*)(W + (size_t)wK * 128 + wN);
    }
    As2[0][aK + 0][aRow] = make_float2(va.x, va.x);
    As2[0][aK + 1][aRow] = make_float2(va.y, va.y);
    As2[0][aK + 2][aRow] = make_float2(va.z, va.z);
    As2[0][aK + 3][aRow] = make_float2(va.w, va.w);
    *(float4*)&Bs[0][wK][wN] = vb;
    __syncthreads();

    for (int kt = 0; kt < NT; kt++) {
        const int cur = kt & 1;
        if (kt + 1 < NT) {
            int gk = (kt + 1) * 8;
            int grow = rowBlk + aRow;
            if (grow < M) {
                va = *(const float4*)(A + (size_t)grow * K + gk + aK);
                if (BN_IN) {
                    int kb = gk + aK;
                    va.x = fmaxf(va.x * __ldg(bscale + kb + 0) + __ldg(bshift + kb + 0), 0.f);
                    va.y = fmaxf(va.y * __ldg(bscale + kb + 1) + __ldg(bshift + kb + 1), 0.f);
                    va.z = fmaxf(va.z * __ldg(bscale + kb + 2) + __ldg(bshift + kb + 2), 0.f);
                    va.w = fmaxf(va.w * __ldg(bscale + kb + 3) + __ldg(bshift + kb + 3), 0.f);
                }
            } else va = make_float4(0.f, 0.f, 0.f, 0.f);
            vb = *(const float4*)(W + (size_t)(gk + wK) * 128 + wN);
        }
        #pragma unroll
        for (int kk = 0; kk < 8; kk++) {
            // A: 4x LDS.128, each yields two packed (v,v) 64-bit operands
            ulonglong2 ap0 = *(const ulonglong2*)&As2[cur][kk][ty * 8];
            ulonglong2 ap1 = *(const ulonglong2*)&As2[cur][kk][ty * 8 + 2];
            ulonglong2 ap2 = *(const ulonglong2*)&As2[cur][kk][ty * 8 + 4];
            ulonglong2 ap3 = *(const ulonglong2*)&As2[cur][kk][ty * 8 + 6];
            ulonglong2 bq0 = *(const ulonglong2*)&Bs[cur][kk][tx * 8];
            ulonglong2 bq1 = *(const ulonglong2*)&Bs[cur][kk][tx * 8 + 4];
            unsigned long long bP0 = bq0.x, bP1 = bq0.y, bP2 = bq1.x, bP3 = bq1.y;
            unsigned long long aP[8] = {ap0.x, ap0.y, ap1.x, ap1.y,
                                        ap2.x, ap2.y, ap3.x, ap3.y};
            #pragma unroll
            for (int r = 0; r < 8; r++) {
                FMA2(accP[r][0], aP[r], bP0);
                FMA2(accP[r][1], aP[r], bP1);
                FMA2(accP[r][2], aP[r], bP2);
                FMA2(accP[r][3], aP[r], bP3);
            }
        }
        if (kt + 1 < NT) {
            const int nxt = cur ^ 1;
            As2[nxt][aK + 0][aRow] = make_float2(va.x, va.x);
            As2[nxt][aK + 1][aRow] = make_float2(va.y, va.y);
            As2[nxt][aK + 2][aRow] = make_float2(va.z, va.z);
            As2[nxt][aK + 3][aRow] = make_float2(va.w, va.w);
            *(float4*)&Bs[nxt][wK][wN] = vb;
        }
        __syncthreads();
    }

    float bias_c[8];
    #pragma unroll
    for (int j = 0; j < 8; j++) bias_c[j] = __ldg(bias + tx * 8 + j);

    float ps[8], pq[8];
    if (STATS) {
        #pragma unroll
        for (int j = 0; j < 8; j++) { ps[j] = 0.f; pq[j] = 0.f; }
    }

    #pragma unroll
    for (int r = 0; r < 8; r++) {
        int grow = rowBlk + ty * 8 + r;
        if (grow < M) {
            float o[8];
            #pragma unroll
            for (int c = 0; c < 4; c++) {
                float lo, hi;
                asm("mov.b64 {%0, %1}, %2;" : "=f"(lo), "=f"(hi) : "l"(accP[r][c]));
                o[2 * c]     = lo;
                o[2 * c + 1] = hi;
            }
            #pragma unroll
            for (int j = 0; j < 8; j++) {
                float v = o[j] + bias_c[j];
                if (STATS) { ps[j] += v; pq[j] += v * v; }
                if (RELU_OUT) v = fmaxf(v, 0.f);
                o[j] = v;
            }
            *(float4*)(C + (size_t)grow * 128 + tx * 8)     = make_float4(o[0], o[1], o[2], o[3]);
            *(float4*)(C + (size_t)grow * 128 + tx * 8 + 4) = make_float4(o[4], o[5], o[6], o[7]);
        }
    }

    if (STATS) {
        #pragma unroll
        for (int j = 0; j < 8; j++) {
            atomicAdd(&s_sum[tx * 8 + j], ps[j]);
            atomicAdd(&s_sq [tx * 8 + j], pq[j]);
        }
        __syncthreads();
        if (tid < 128) {
            atomicAdd(gsum + tid, s_sum[tid]);
            atomicAdd(gsq  + tid, s_sq[tid]);
        }
    }
}

// ---------------- BN finalize ----------------
__global__ void bn_finalize_kernel(const float* __restrict__ cs, const float* __restrict__ cq,
                                   const float* __restrict__ g, const float* __restrict__ b,
                                   int N, float* __restrict__ scale, float* __restrict__ shift)
{
    int j = threadIdx.x;
    float invN = 1.f / (float)N;
    float mean = cs[j] * invN;
    float var  = cq[j] * invN - mean * mean;
    float inv  = rsqrtf(var + BN_EPS);
    float sc   = g[j] * inv;
    scale[j] = sc;
    shift[j] = b[j] - mean * sc;
}

// ---------------- global add pool ----------------
__global__ void __launch_bounds__(256) pool_kernel(
    const float* __restrict__ h, const int* __restrict__ batch,
    float* __restrict__ pooled, int N)
{
    const int lane = threadIdx.x & 31;
    const int warp = (blockIdx.x * blockDim.x + threadIdx.x) >> 5;
    const int CHUNK = 64;
    int n0 = warp * CHUNK;
    if (n0 >= N) return;
    int n1 = n0 + CHUNK; if (n1 > N) n1 = N;
    const int f = lane * 4;

    int cur = __ldg(batch + n0);
    float4 acc = make_float4(0.f, 0.f, 0.f, 0.f);
    for (int n = n0; n < n1; n++) {
        int b = __ldg(batch + n);
        if (b != cur) {
            red_add_v4(pooled + (size_t)cur * H + f, acc);
            acc = make_float4(0.f, 0.f, 0.f, 0.f);
            cur = b;
        }
        float4 v = *(const float4*)(h + (size_t)n * H + f);
        acc.x += v.x; acc.y += v.y; acc.z += v.z; acc.w += v.w;
    }
    red_add_v4(pooled + (size_t)cur * H + f, acc);
}

// ---------------- final FC ----------------
__global__ void final_gemm_kernel(const float* __restrict__ pooled,
                                  const float* __restrict__ fcw, const float* __restrict__ fcb,
                                  float* __restrict__ out, int G)
{
    __shared__ float row[H];
    int g = blockIdx.x;
    row[threadIdx.x] = pooled[(size_t)g * H + threadIdx.x];
    __syncthreads();
    if (threadIdx.x < 10) {
        float acc = fcb[threadIdx.x];
        #pragma unroll 8
        for (int k = 0; k < H; k++)
            acc += row[k] * fcw[k * 10 + threadIdx.x];
        out[g * 10 + threadIdx.x] = acc;
    }
}

// ---------------- launch ----------------
extern "C" void kernel_launch(void* const* d_in, const int* in_sizes, int n_in,
                              void* d_out, int out_size)
{
    const float* x      = (const float*)d_in[0];
    const float* ea     = (const float*)d_in[1];
    const float* node_w = (const float*)d_in[2];
    const float* node_b = (const float*)d_in[3];
    const float* edge_w = (const float*)d_in[4];
    const float* edge_b = (const float*)d_in[5];
    const float* lin1_w = (const float*)d_in[6];
    const float* lin1_b = (const float*)d_in[7];
    const float* bn_g   = (const float*)d_in[8];
    const float* bn_b   = (const float*)d_in[9];
    const float* lin2_w = (const float*)d_in[10];
    const float* lin2_b = (const float*)d_in[11];
    const float* fc_w   = (const float*)d_in[12];
    const float* fc_b   = (const float*)d_in[13];
    const int* ei       = (const int*)d_in[14];
    const int* batch    = (const int*)d_in[15];

    const int N = in_sizes[0] / XD;
    const int E = in_sizes[1] / ED;
    const int G = out_size / 10;

    float *hP, *tP, *h1P, *plP, *csP, *cqP, *scP, *shP;
    __half* esP;
    int *ssrcP, *epermP, *cntP, *rowP, *ofsP;
    cudaGetSymbolAddress((void**)&hP,    g_h);
    cudaGetSymbolAddress((void**)&tP,    g_t);
    cudaGetSymbolAddress((void**)&h1P,   g_h1);
    cudaGetSymbolAddress((void**)&plP,   g_pooled);
    cudaGetSymbolAddress((void**)&csP,   g_colsum);
    cudaGetSymbolAddress((void**)&cqP,   g_colsumsq);
    cudaGetSymbolAddress((void**)&scP,   g_scale);
    cudaGetSymbolAddress((void**)&shP,   g_shift);
    cudaGetSymbolAddress((void**)&esP,   g_esort);
    cudaGetSymbolAddress((void**)&ssrcP, g_ssrc);
    cudaGetSymbolAddress((void**)&epermP,g_eperm);
    cudaGetSymbolAddress((void**)&cntP,  g_cnt);
    cudaGetSymbolAddress((void**)&rowP,  g_row);
    cudaGetSymbolAddress((void**)&ofsP,  g_ofs);

    const int gemmGrid = (N + 127) / 128;

    // ---- CSR build + edge-MLP precompute (ONCE; reused by all 3 layers) ----
    cudaMemsetAsync(cntP, 0, N * sizeof(int));
    hist_kernel<<<(E + 255) / 256, 256>>>(ei, cntP, E);
    prefix_kernel<<<1, 1024>>>(cntP, rowP, ofsP, N, E);
    scatter_kernel<<<(E + 255) / 256, 256>>>(ei, ofsP, ssrcP, epermP, E);
    ecomp_kernel<<<(E + 127) / 128, 256>>>(ea, epermP, edge_w, edge_b, esP, E);

    // node encoder: h = x @ node_w + node_b
    gemm_k<XD, false, false, false><<<gemmGrid, 256>>>(
        x, node_w, node_b, hP, N, nullptr, nullptr, nullptr, nullptr);

    for (int l = 0; l < 3; l++) {
        // t = h + segment_sum(relu(h[src] + e)); also zeroes BN stat accumulators
        aggr_kernel<<<(N * 32 + 255) / 256, 256>>>(
            hP, tP, esP, ssrcP, rowP, N, csP, cqP);
        // h1 = t @ W1 + b1, with column sum/sumsq accumulation
        gemm_k<H, false, false, true><<<gemmGrid, 256>>>(
            tP, lin1_w + (size_t)l * H * H, lin1_b + l * H, h1P, N,
            nullptr, nullptr, csP, cqP);
        // BN scale/shift
        bn_finalize_kernel<<<1, H>>>(csP, cqP, bn_g + l * H, bn_b + l * H, N, scP, shP);
        // h = relu( relu(bn(h1)) @ W2 + b2 )
        gemm_k<H, true, true, false><<<gemmGrid, 256>>>(
            h1P, lin2_w + (size_t)l * H * H, lin2_b + l * H, hP, N,
            scP, shP, nullptr, nullptr);
    }

    // pooled = segment_sum(h, batch)
    cudaMemsetAsync(plP, 0, (size_t)G * H * sizeof(float));
    int poolWarps = (N + 63) / 64;
    pool_kernel<<<(poolWarps + 7) / 8, 256>>>(hP, batch, plP, N);

    // out = pooled @ fc_w + fc_b
    final_gemm_kernel<<<G, H>>>(plP, fc_w, fc_b, (float*)d_out, G);
}